// round 1
// baseline (speedup 1.0000x reference)
#include <cuda_runtime.h>
#include <cuda_bf16.h>

// ---------------------------------------------------------------------------
// ESN: h' = (1-a)h + a*tanh(x_t @ W_in + h @ W_r), a=0.9 (a=1 at t=0, h0=0)
// B=256, T=2048, D=128, H=1024; keep last 20 h, then linear [20480 -> 32].
//
// Strategy:
//  - Augmented K = 1024(h) + 128(x) = 1152, W_aug = [W_r ; W_in].
//  - bf16 split (hi/lo) 3-product GEMM with fp32 accum (Markidis) for accuracy.
//  - Persistent 128-CTA kernel, one custom grid barrier per step.
//  - h stored in mma A-fragment layout (hi/lo bf16), double buffered, all
//    traffic via L2 (.cg) so no cross-SM L1 staleness.
//  - W fragments resident in shared memory for all 2048 steps.
// ---------------------------------------------------------------------------

#define TT     2048
#define BB     256
#define HH     1024
#define DD     128
#define NCTA   128
#define KCH    64          // h K-chunks (1024/16)
#define KCX    8           // x K-chunks (128/16)
#define KCT    72          // total K-chunks
#define KEEP0  2028        // first kept step
#define NLAST  20
#define KOUT   (NLAST*HH)  // 20480

#define SMEM_BYTES (4*2*KCT*32*8)   // 4 n8-groups * 2 splits * 72 kc * 32 lanes * uint2

// ---- device globals (scratch; no allocations allowed) ----------------------
__device__ __align__(16) uint4 g_X[(size_t)TT*2*16*KCX*32];   // x fragments (hi/lo), 268MB
__device__ __align__(16) uint2 g_W[128*2*KCT*32];             // W fragments (hi/lo)
__device__ __align__(16) uint4 g_H[2][2][16][KCH][32];        // h frags: [buf][split][m16][kc][lane]
__device__ float    g_hist[(size_t)NLAST*BB*HH];              // kept states, fp32
__device__ unsigned g_count;
__device__ unsigned g_epoch;

// ---- helpers ---------------------------------------------------------------
__device__ __forceinline__ unsigned pk2(float a, float b) {
    __nv_bfloat162 t = __floats2bfloat162_rn(a, b);   // x = a (low), y = b (high)
    return reinterpret_cast<unsigned&>(t);
}
__device__ __forceinline__ float rlo(float v) {       // residual after bf16 round
    return v - __bfloat162float(__float2bfloat16_rn(v));
}
__device__ __forceinline__ float bsel(unsigned u, int hi) {
    unsigned short s = (unsigned short)(hi ? (u >> 16) : (u & 0xffffu));
    __nv_bfloat16 b = reinterpret_cast<__nv_bfloat16&>(s);
    return __bfloat162float(b);
}
__device__ __forceinline__ void mma16816(float* c, const uint4 a, const uint2 b) {
    asm volatile(
        "mma.sync.aligned.m16n8k16.row.col.f32.bf16.bf16.f32 "
        "{%0,%1,%2,%3}, {%4,%5,%6,%7}, {%8,%9}, {%0,%1,%2,%3};\n"
        : "+f"(c[0]), "+f"(c[1]), "+f"(c[2]), "+f"(c[3])
        : "r"(a.x), "r"(a.y), "r"(a.z), "r"(a.w), "r"(b.x), "r"(b.y));
}

__device__ __forceinline__ void grid_barrier(unsigned want) {
    __threadfence();
    __syncthreads();
    if (threadIdx.x == 0) {
        unsigned arr = atomicAdd(&g_count, 1u) + 1u;
        if (arr == want * NCTA) {
            atomicExch(&g_epoch, want);
        } else {
            while (*(volatile unsigned*)&g_epoch < want) { }
        }
        __threadfence();
    }
    __syncthreads();
}

// ---- prep kernels ----------------------------------------------------------
__global__ void prep_zero() { g_count = 0u; g_epoch = 0u; }

// Build W fragments: W_aug[k][n], k<1024 -> w_r[k][n], k>=1024 -> w_in[k-1024][n]
// Layout: g_W[((n8*2 + split)*KCT + kc)*32 + lane] = {pair(k0,k0+1), pair(k0+8,k0+9)}
__global__ void prep_w(const float* __restrict__ w_r, const float* __restrict__ w_in) {
    int i = blockIdx.x * blockDim.x + threadIdx.x;
    if (i >= 128 * KCT * 32) return;
    int lane = i & 31;
    int kc   = (i >> 5) % KCT;
    int n8   = i / (KCT * 32);
    int n    = n8 * 8 + (lane >> 2);
    int k0   = kc * 16 + (lane & 3) * 2;
    float v[4];
#pragma unroll
    for (int r = 0; r < 4; r++) {
        int k = k0 + ((r >> 1) * 8) + (r & 1);   // k0, k0+1, k0+8, k0+9
        v[r] = (k < HH) ? w_r[(size_t)k * HH + n] : w_in[(size_t)(k - HH) * HH + n];
    }
    g_W[((n8 * 2 + 0) * KCT + kc) * 32 + lane] =
        make_uint2(pk2(v[0], v[1]), pk2(v[2], v[3]));
    g_W[((n8 * 2 + 1) * KCT + kc) * 32 + lane] =
        make_uint2(pk2(rlo(v[0]), rlo(v[1])), pk2(rlo(v[2]), rlo(v[3])));
}

// Build x fragments: A rows = batch, cols = d; frag layout per (t, split, m16, kcx, lane)
__global__ void prep_x(const float* __restrict__ x) {
    size_t i = (size_t)blockIdx.x * blockDim.x + threadIdx.x;
    if (i >= (size_t)TT * 16 * KCX * 32) return;
    int lane = (int)(i & 31);
    int kcx  = (int)((i >> 5) & 7);
    int m16  = (int)((i >> 8) & 15);
    int t    = (int)(i >> 12);
    int b = m16 * 16 + (lane >> 2);
    int d = kcx * 16 + (lane & 3) * 2;
    const float* p0 = x + ((size_t)b * TT + t) * DD + d;
    const float* p1 = x + ((size_t)(b + 8) * TT + t) * DD + d;
    float2 a0 = *(const float2*)(p0);       // (r,   c..c+1)
    float2 a1 = *(const float2*)(p1);       // (r+8, c..c+1)
    float2 a2 = *(const float2*)(p0 + 8);   // (r,   c+8..c+9)
    float2 a3 = *(const float2*)(p1 + 8);   // (r+8, c+8..c+9)
    uint4 hi = make_uint4(pk2(a0.x, a0.y), pk2(a1.x, a1.y),
                          pk2(a2.x, a2.y), pk2(a3.x, a3.y));
    uint4 lo = make_uint4(pk2(rlo(a0.x), rlo(a0.y)), pk2(rlo(a1.x), rlo(a1.y)),
                          pk2(rlo(a2.x), rlo(a2.y)), pk2(rlo(a3.x), rlo(a3.y)));
    size_t bh = ((((size_t)t * 2 + 0) * 16 + m16) * KCX + kcx) * 32 + lane;
    size_t bl = ((((size_t)t * 2 + 1) * 16 + m16) * KCX + kcx) * 32 + lane;
    g_X[bh] = hi;
    g_X[bl] = lo;
}

// ---- main persistent recurrence kernel ------------------------------------
__global__ void __launch_bounds__(256, 1) esn_main() {
    extern __shared__ __align__(16) uint2 sW[];   // [n8l 4][split 2][kc 72][lane 32]
    const int tid   = threadIdx.x;
    const int lane  = tid & 31;
    const int warp  = tid >> 5;
    const int cta_n = blockIdx.x & 31;    // 32 column tiles (BN=32)
    const int cta_m = blockIdx.x >> 5;    // 4 row tiles (BM=64)

    // Load this CTA's W column tile into smem (resident for all steps)
    {
        const uint4* src = reinterpret_cast<const uint4*>(g_W + (size_t)cta_n * 4 * 2 * KCT * 32);
        uint4* dst = reinterpret_cast<uint4*>(sW);
        const int tot = (4 * 2 * KCT * 32) / 2;   // uint4 count = 9216
        for (int i = tid; i < tot; i += 256) dst[i] = src[i];
    }
    __syncthreads();

    const int warp_m = warp >> 1;                 // 0..3
    const int warp_n = warp & 1;                  // 0..1
    const int m16 = cta_m * 4 + warp_m;           // A-frag row tile
    const int kcw = cta_n * 2 + warp_n;           // h-frag chunk this warp owns

    // smem B-fragment base pointers: [f][split]
    const uint2* pB00 = sW + ((((warp_n * 2 + 0) * 2 + 0) * KCT) * 32) + lane;
    const uint2* pB01 = sW + ((((warp_n * 2 + 0) * 2 + 1) * KCT) * 32) + lane;
    const uint2* pB10 = sW + ((((warp_n * 2 + 1) * 2 + 0) * KCT) * 32) + lane;
    const uint2* pB11 = sW + ((((warp_n * 2 + 1) * 2 + 1) * KCT) * 32) + lane;

    for (int t = 0; t < TT; t++) {
        float c0[4] = {0.f, 0.f, 0.f, 0.f};
        float c1[4] = {0.f, 0.f, 0.f, 0.f};

        if (t > 0) {
            const int rb = t & 1;
            const uint4* Ah = &g_H[rb][0][m16][0][lane];
            const uint4* Al = &g_H[rb][1][m16][0][lane];
#pragma unroll 8
            for (int kc = 0; kc < KCH; kc++) {
                uint4 ah = __ldcg(Ah + (size_t)kc * 32);
                uint4 al = __ldcg(Al + (size_t)kc * 32);
                uint2 b0h = pB00[kc * 32];
                uint2 b0l = pB01[kc * 32];
                uint2 b1h = pB10[kc * 32];
                uint2 b1l = pB11[kc * 32];
                mma16816(c0, ah, b0h);
                mma16816(c0, ah, b0l);
                mma16816(c0, al, b0h);
                mma16816(c1, ah, b1h);
                mma16816(c1, ah, b1l);
                mma16816(c1, al, b1h);
            }
        }
        {   // x part (K chunks 64..71)
            const uint4* Xh = &g_X[(((size_t)t * 2 + 0) * 16 + m16) * KCX * 32 + lane];
            const uint4* Xl = &g_X[(((size_t)t * 2 + 1) * 16 + m16) * KCX * 32 + lane];
#pragma unroll
            for (int kx = 0; kx < KCX; kx++) {
                uint4 ah = __ldg(Xh + (size_t)kx * 32);
                uint4 al = __ldg(Xl + (size_t)kx * 32);
                int kc = KCH + kx;
                uint2 b0h = pB00[kc * 32];
                uint2 b0l = pB01[kc * 32];
                uint2 b1h = pB10[kc * 32];
                uint2 b1l = pB11[kc * 32];
                mma16816(c0, ah, b0h);
                mma16816(c0, ah, b0l);
                mma16816(c0, al, b0h);
                mma16816(c1, ah, b1h);
                mma16816(c1, ah, b1l);
                mma16816(c1, al, b1h);
            }
        }

        // blend + split + store (fragment layout, slot == own lane)
        const int wb = (t + 1) & 1;
        uint4 ph, pl;
        if (t > 0) {
            const int rb = t & 1;
            ph = __ldcg(&g_H[rb][0][m16][kcw][lane]);
            pl = __ldcg(&g_H[rb][1][m16][kcw][lane]);
        }
        float hv[8];
        {
            const unsigned* eh = &ph.x;
            const unsigned* el = &pl.x;
#pragma unroll
            for (int f = 0; f < 2; f++) {
                const float* cc = f ? c1 : c0;
#pragma unroll
                for (int j = 0; j < 4; j++) {
                    float th = tanhf(cc[j]);
                    float hn;
                    if (t == 0) {
                        hn = th;
                    } else {
                        int reg = 2 * f + (j >> 1);
                        float pv = bsel(eh[reg], j & 1) + bsel(el[reg], j & 1);
                        hn = 0.1f * pv + 0.9f * th;
                    }
                    hv[f * 4 + j] = hn;
                }
            }
        }
        uint4 nh = make_uint4(pk2(hv[0], hv[1]), pk2(hv[2], hv[3]),
                              pk2(hv[4], hv[5]), pk2(hv[6], hv[7]));
        uint4 nl = make_uint4(pk2(rlo(hv[0]), rlo(hv[1])), pk2(rlo(hv[2]), rlo(hv[3])),
                              pk2(rlo(hv[4]), rlo(hv[5])), pk2(rlo(hv[6]), rlo(hv[7])));
        __stcg(&g_H[wb][0][m16][kcw][lane], nh);
        __stcg(&g_H[wb][1][m16][kcw][lane], nl);

        if (t >= KEEP0) {
            int r0 = cta_m * 64 + warp_m * 16 + (lane >> 2);
            int cb = cta_n * 32 + warp_n * 16 + (lane & 3) * 2;
            size_t base = (size_t)(t - KEEP0) * BB * HH;
            *(float2*)&g_hist[base + (size_t)(r0)     * HH + cb]     = make_float2(hv[0], hv[1]);
            *(float2*)&g_hist[base + (size_t)(r0 + 8) * HH + cb]     = make_float2(hv[2], hv[3]);
            *(float2*)&g_hist[base + (size_t)(r0)     * HH + cb + 8] = make_float2(hv[4], hv[5]);
            *(float2*)&g_hist[base + (size_t)(r0 + 8) * HH + cb + 8] = make_float2(hv[6], hv[7]);
        }

        if (t < TT - 1) grid_barrier((unsigned)(t + 1));
    }
}

// ---- readout: out[b][o] = sum_k hist_feat[b][k] * lin_w[o][k] + lin_b[o] ---
__global__ void readout(const float* __restrict__ lw, const float* __restrict__ lb,
                        float* __restrict__ out) {
    int b    = blockIdx.x;
    int warp = threadIdx.x >> 5;
    int lane = threadIdx.x & 31;
    int o0   = warp * 4;
    float a0 = 0.f, a1 = 0.f, a2 = 0.f, a3 = 0.f;
    for (int k = lane; k < KOUT; k += 32) {
        int s = k >> 10, j = k & (HH - 1);
        float h = g_hist[(size_t)s * BB * HH + (size_t)b * HH + j];
        a0 += h * __ldg(&lw[(size_t)(o0 + 0) * KOUT + k]);
        a1 += h * __ldg(&lw[(size_t)(o0 + 1) * KOUT + k]);
        a2 += h * __ldg(&lw[(size_t)(o0 + 2) * KOUT + k]);
        a3 += h * __ldg(&lw[(size_t)(o0 + 3) * KOUT + k]);
    }
#pragma unroll
    for (int off = 16; off > 0; off >>= 1) {
        a0 += __shfl_down_sync(0xffffffffu, a0, off);
        a1 += __shfl_down_sync(0xffffffffu, a1, off);
        a2 += __shfl_down_sync(0xffffffffu, a2, off);
        a3 += __shfl_down_sync(0xffffffffu, a3, off);
    }
    if (lane == 0) {
        out[b * 32 + o0 + 0] = a0 + lb[o0 + 0];
        out[b * 32 + o0 + 1] = a1 + lb[o0 + 1];
        out[b * 32 + o0 + 2] = a2 + lb[o0 + 2];
        out[b * 32 + o0 + 3] = a3 + lb[o0 + 3];
    }
}

// ---- launch ----------------------------------------------------------------
extern "C" void kernel_launch(void* const* d_in, const int* in_sizes, int n_in,
                              void* d_out, int out_size) {
    const float* x    = (const float*)d_in[0];   // [256,2048,128]
    const float* w_in = (const float*)d_in[1];   // [128,1024]
    const float* w_r  = (const float*)d_in[2];   // [1024,1024]
    const float* lw   = (const float*)d_in[3];   // [32,20480]
    const float* lb   = (const float*)d_in[4];   // [32]
    float* out = (float*)d_out;                  // [256,32]

    cudaFuncSetAttribute(esn_main, cudaFuncAttributeMaxDynamicSharedMemorySize, SMEM_BYTES);

    prep_zero<<<1, 1>>>();
    prep_w<<<(128 * KCT * 32 + 255) / 256, 256>>>(w_r, w_in);
    prep_x<<<(int)(((size_t)TT * 16 * KCX * 32) / 256), 256>>>(x);
    esn_main<<<NCTA, 256, SMEM_BYTES>>>();
    readout<<<BB, 256>>>(lw, lb, out);
}

// round 2
// speedup vs baseline: 2.3384x; 2.3384x over previous
#include <cuda_runtime.h>
#include <cuda_fp16.h>

// ---------------------------------------------------------------------------
// ESN recurrence, single-fp16 tensor-core version.
//  h' = 0.1*h + 0.9*tanh(x_t @ W_in + h @ W_r)   (t=0: h' = tanh(x_0 @ W_in))
//  B=256, T=2048, D=128, H=1024; keep last 20 states; linear 20480->32.
//
//  - Augmented K = 1152 (h:1024 + x:128), W_aug=[W_r;W_in] as fp16 frags in smem.
//  - Everything single fp16 (error budget: ~2e-4 final vs 1e-3 gate).
//  - 128 persistent CTAs (BM=64, BN=32), 8 warps: 4 m16-rows x 2 K-halves.
//    Each warp: full N=32, half of K -> zero A duplication at L2.
//  - K-half partial C reduced via smem; each warp then owns one 16-col chunk.
//  - h double-buffered in global as mma A-fragments (uint4 of fp16), .cg only.
//  - Grid barrier: red.release.gpu + ld.acquire.gpu spin, 1 per step.
// ---------------------------------------------------------------------------

#define TT     2048
#define BB     256
#define HH     1024
#define DD     128
#define NCTA   128
#define THREADS 256
#define KC2T   36          // kc-pairs total (72 kc of 16)
#define KEEP0  2028
#define NLAST  20
#define KOUT   (NLAST*HH)

#define SMEM_W_BYTES   (4*KC2T*32*16)    // 73728: [n8 4][kc2 36][lane 32] uint4
#define SMEM_RED_BYTES (4*2*2*32*16)     // 8192
#define SMEM_TOTAL     (SMEM_W_BYTES + SMEM_RED_BYTES)

// ---- device globals --------------------------------------------------------
__device__ __align__(16) uint4 g_X[(size_t)TT*16*8*32];   // x frags fp16, 134MB
__device__ __align__(16) uint4 g_W[128*KC2T*32];          // W frags fp16 (kc-pair packed)
__device__ __align__(16) uint4 g_H[2][16][64][32];        // h frags: [buf][m16][kc][lane]
__device__ float    g_hist[(size_t)NLAST*BB*HH];
__device__ unsigned g_count;

// ---- helpers ---------------------------------------------------------------
__device__ __forceinline__ unsigned pkh(float a, float b) {
    __half2 t = __floats2half2_rn(a, b);
    return reinterpret_cast<unsigned&>(t);
}
__device__ __forceinline__ float2 uph(unsigned u) {
    __half2 t = reinterpret_cast<__half2&>(u);
    return __half22float2(t);
}
__device__ __forceinline__ void mma16816(float* c, const uint4 a, const uint2 b) {
    asm volatile(
        "mma.sync.aligned.m16n8k16.row.col.f32.f16.f16.f32 "
        "{%0,%1,%2,%3}, {%4,%5,%6,%7}, {%8,%9}, {%0,%1,%2,%3};\n"
        : "+f"(c[0]), "+f"(c[1]), "+f"(c[2]), "+f"(c[3])
        : "r"(a.x), "r"(a.y), "r"(a.z), "r"(a.w), "r"(b.x), "r"(b.y));
}

// mma over CNT kc-pairs: A frags at A[kc][32] (kc relative), B at sW[n8][kc2][lane].
// 4-deep register prefetch ring on A to cover L2 latency.
template<int CNT>
__device__ __forceinline__ void mma_span(float* c, const uint4* __restrict__ A,
                                         const uint4* __restrict__ sW4,
                                         int kc2base, int lane) {
    uint4 ab[4][2];
#pragma unroll
    for (int i = 0; i < 4 && i < CNT; i++) {
        ab[i][0] = __ldcg(A + (size_t)(2*i)   * 32);
        ab[i][1] = __ldcg(A + (size_t)(2*i+1) * 32);
    }
#pragma unroll
    for (int j = 0; j < CNT; j++) {
        uint4 b0 = sW4[(size_t)(0*KC2T + kc2base + j)*32 + lane];
        uint4 b1 = sW4[(size_t)(1*KC2T + kc2base + j)*32 + lane];
        uint4 b2 = sW4[(size_t)(2*KC2T + kc2base + j)*32 + lane];
        uint4 b3 = sW4[(size_t)(3*KC2T + kc2base + j)*32 + lane];
        uint4 a0 = ab[j & 3][0];
        uint4 a1 = ab[j & 3][1];
        if (j + 4 < CNT) {
            ab[j & 3][0] = __ldcg(A + (size_t)(2*(j+4))   * 32);
            ab[j & 3][1] = __ldcg(A + (size_t)(2*(j+4)+1) * 32);
        }
        mma16816(c + 0,  a0, make_uint2(b0.x, b0.y));
        mma16816(c + 0,  a1, make_uint2(b0.z, b0.w));
        mma16816(c + 4,  a0, make_uint2(b1.x, b1.y));
        mma16816(c + 4,  a1, make_uint2(b1.z, b1.w));
        mma16816(c + 8,  a0, make_uint2(b2.x, b2.y));
        mma16816(c + 8,  a1, make_uint2(b2.z, b2.w));
        mma16816(c + 12, a0, make_uint2(b3.x, b3.y));
        mma16816(c + 12, a1, make_uint2(b3.z, b3.w));
    }
}

// ---- prep kernels ----------------------------------------------------------
__global__ void prep_zero() { g_count = 0u; }

// W_aug[k][n]: k<1024 -> w_r[k][n], k>=1024 -> w_in[k-1024][n].  fp16 frags,
// kc-pairs packed: g_W[(n8*KC2T + kc2)*32 + lane] = {frag(kc=2kc2), frag(2kc2+1)}
__global__ void prep_w(const float* __restrict__ w_r, const float* __restrict__ w_in) {
    int i = blockIdx.x * blockDim.x + threadIdx.x;
    if (i >= 128 * KC2T * 32) return;
    int lane = i & 31;
    int kc2  = (i >> 5) % KC2T;
    int n8   = i / (KC2T * 32);
    int n    = n8 * 8 + (lane >> 2);
    unsigned u[4];
#pragma unroll
    for (int s = 0; s < 2; s++) {
        int kc = 2 * kc2 + s;
        int k0 = kc * 16 + (lane & 3) * 2;
        float v[4];
#pragma unroll
        for (int r = 0; r < 4; r++) {
            int k = k0 + ((r >> 1) * 8) + (r & 1);   // k0, k0+1, k0+8, k0+9
            v[r] = (k < HH) ? w_r[(size_t)k * HH + n] : w_in[(size_t)(k - HH) * HH + n];
        }
        u[2*s + 0] = pkh(v[0], v[1]);
        u[2*s + 1] = pkh(v[2], v[3]);
    }
    g_W[i] = make_uint4(u[0], u[1], u[2], u[3]);
}

// x fragments (single fp16): g_X[((t*16+m16)*8+kcx)*32 + lane]
__global__ void prep_x(const float* __restrict__ x) {
    size_t i = (size_t)blockIdx.x * blockDim.x + threadIdx.x;
    if (i >= (size_t)TT * 16 * 8 * 32) return;
    int lane = (int)(i & 31);
    int kcx  = (int)((i >> 5) & 7);
    int m16  = (int)((i >> 8) & 15);
    int t    = (int)(i >> 12);
    int b = m16 * 16 + (lane >> 2);
    int d = kcx * 16 + (lane & 3) * 2;
    const float* p0 = x + ((size_t)b * TT + t) * DD + d;
    const float* p1 = p0 + (size_t)8 * TT * DD;
    float2 a0 = *(const float2*)(p0);
    float2 a1 = *(const float2*)(p1);
    float2 a2 = *(const float2*)(p0 + 8);
    float2 a3 = *(const float2*)(p1 + 8);
    g_X[i] = make_uint4(pkh(a0.x, a0.y), pkh(a1.x, a1.y),
                        pkh(a2.x, a2.y), pkh(a3.x, a3.y));
}

// ---- main persistent kernel ------------------------------------------------
__global__ void __launch_bounds__(THREADS, 1) esn_main() {
    extern __shared__ __align__(16) unsigned char smem[];
    uint4*  sW4  = reinterpret_cast<uint4*>(smem);
    float4* sred = reinterpret_cast<float4*>(smem + SMEM_W_BYTES);

    const int tid   = threadIdx.x;
    const int lane  = tid & 31;
    const int warp  = tid >> 5;
    const int m     = warp & 3;          // m16 within CTA
    const int h     = warp >> 2;         // K-half (0: kc 0..35, 1: kc 36..71)
    const int peer  = 1 - h;
    const int cta_n = blockIdx.x & 31;   // 32 column tiles (BN=32)
    const int cta_m = blockIdx.x >> 5;   // 4 row tiles (BM=64)
    const int m16g  = cta_m * 4 + m;
    const int kcw   = cta_n * 2 + h;     // h-fragment column chunk this warp owns

    // Load W column tile into smem (resident for all steps)
    {
        const uint4* src = g_W + (size_t)cta_n * 4 * KC2T * 32;
        for (int i = tid; i < 4 * KC2T * 32; i += THREADS) sW4[i] = src[i];
    }
    __syncthreads();

    for (int t = 0; t < TT; t++) {
        float c[16];
#pragma unroll
        for (int i = 0; i < 16; i++) c[i] = 0.f;

        const int rb = t & 1;
        if (h == 0) {
            if (t > 0) {
                const uint4* A = &g_H[rb][m16g][0][lane];
                mma_span<18>(c, A, sW4, 0, lane);          // kc 0..35
            }
        } else {
            if (t > 0) {
                const uint4* A = &g_H[rb][m16g][36][lane];
                mma_span<14>(c, A, sW4, 18, lane);         // kc 36..63
            }
            const uint4* X = &g_X[(((size_t)t * 16 + m16g) * 8) * 32 + lane];
            mma_span<4>(c, X, sW4, 32, lane);              // kc 64..71 (x part)
        }

        // K-half reduction: hand my peer-chunk partials over, take mine.
        sred[(size_t)((m * 2 + peer) * 2 + 0) * 32 + lane] =
            make_float4(c[8*peer+0], c[8*peer+1], c[8*peer+2], c[8*peer+3]);
        sred[(size_t)((m * 2 + peer) * 2 + 1) * 32 + lane] =
            make_float4(c[8*peer+4], c[8*peer+5], c[8*peer+6], c[8*peer+7]);
        __syncthreads();
        float4 r0 = sred[(size_t)((m * 2 + h) * 2 + 0) * 32 + lane];
        float4 r1 = sred[(size_t)((m * 2 + h) * 2 + 1) * 32 + lane];
        float fin[8] = { c[8*h+0] + r0.x, c[8*h+1] + r0.y,
                         c[8*h+2] + r0.z, c[8*h+3] + r0.w,
                         c[8*h+4] + r1.x, c[8*h+5] + r1.y,
                         c[8*h+6] + r1.z, c[8*h+7] + r1.w };

        // blend with old h, pack, store new h fragment (this warp owns chunk kcw)
        float hv[8];
        if (t == 0) {
#pragma unroll
            for (int i = 0; i < 8; i++) hv[i] = tanhf(fin[i]);
        } else {
            uint4 ph = __ldcg(&g_H[rb][m16g][kcw][lane]);
            float2 o0 = uph(ph.x), o1 = uph(ph.y), o2 = uph(ph.z), o3 = uph(ph.w);
            float old[8] = { o0.x, o0.y, o1.x, o1.y, o2.x, o2.y, o3.x, o3.y };
#pragma unroll
            for (int i = 0; i < 8; i++) hv[i] = 0.1f * old[i] + 0.9f * tanhf(fin[i]);
        }
        uint4 nh = make_uint4(pkh(hv[0], hv[1]), pkh(hv[2], hv[3]),
                              pkh(hv[4], hv[5]), pkh(hv[6], hv[7]));
        __stcg(&g_H[(t + 1) & 1][m16g][kcw][lane], nh);

        if (t >= KEEP0) {
            int r0r = cta_m * 64 + m * 16 + (lane >> 2);
            int cb  = cta_n * 32 + h * 16 + (lane & 3) * 2;
            size_t base = (size_t)(t - KEEP0) * BB * HH;
            *(float2*)&g_hist[base + (size_t)(r0r)     * HH + cb]     = make_float2(hv[0], hv[1]);
            *(float2*)&g_hist[base + (size_t)(r0r + 8) * HH + cb]     = make_float2(hv[2], hv[3]);
            *(float2*)&g_hist[base + (size_t)(r0r)     * HH + cb + 8] = make_float2(hv[4], hv[5]);
            *(float2*)&g_hist[base + (size_t)(r0r + 8) * HH + cb + 8] = make_float2(hv[6], hv[7]);
        }

        // chip-wide step barrier (release-arrive / acquire-spin, monotone count)
        if (t < TT - 1) {
            __syncthreads();
            if (tid == 0) {
                unsigned* cp = &g_count;
                asm volatile("red.release.gpu.global.add.u32 [%0], %1;"
                             :: "l"(cp), "r"(1u) : "memory");
                unsigned want = (unsigned)(t + 1) * NCTA;
                unsigned v;
                do {
                    asm volatile("ld.acquire.gpu.global.u32 %0, [%1];"
                                 : "=r"(v) : "l"(cp) : "memory");
                } while (v < want);
            }
            __syncthreads();
        }
    }
}

// ---- readout ---------------------------------------------------------------
__global__ void readout(const float* __restrict__ lw, const float* __restrict__ lb,
                        float* __restrict__ out) {
    int b    = blockIdx.x;
    int warp = threadIdx.x >> 5;
    int lane = threadIdx.x & 31;
    int o0   = warp * 4;
    float a0 = 0.f, a1 = 0.f, a2 = 0.f, a3 = 0.f;
    for (int k = lane; k < KOUT; k += 32) {
        int s = k >> 10, j = k & (HH - 1);
        float hval = g_hist[(size_t)s * BB * HH + (size_t)b * HH + j];
        a0 += hval * __ldg(&lw[(size_t)(o0 + 0) * KOUT + k]);
        a1 += hval * __ldg(&lw[(size_t)(o0 + 1) * KOUT + k]);
        a2 += hval * __ldg(&lw[(size_t)(o0 + 2) * KOUT + k]);
        a3 += hval * __ldg(&lw[(size_t)(o0 + 3) * KOUT + k]);
    }
#pragma unroll
    for (int off = 16; off > 0; off >>= 1) {
        a0 += __shfl_down_sync(0xffffffffu, a0, off);
        a1 += __shfl_down_sync(0xffffffffu, a1, off);
        a2 += __shfl_down_sync(0xffffffffu, a2, off);
        a3 += __shfl_down_sync(0xffffffffu, a3, off);
    }
    if (lane == 0) {
        out[b * 32 + o0 + 0] = a0 + lb[o0 + 0];
        out[b * 32 + o0 + 1] = a1 + lb[o0 + 1];
        out[b * 32 + o0 + 2] = a2 + lb[o0 + 2];
        out[b * 32 + o0 + 3] = a3 + lb[o0 + 3];
    }
}

// ---- launch ----------------------------------------------------------------
extern "C" void kernel_launch(void* const* d_in, const int* in_sizes, int n_in,
                              void* d_out, int out_size) {
    const float* x    = (const float*)d_in[0];   // [256,2048,128]
    const float* w_in = (const float*)d_in[1];   // [128,1024]
    const float* w_r  = (const float*)d_in[2];   // [1024,1024]
    const float* lw   = (const float*)d_in[3];   // [32,20480]
    const float* lb   = (const float*)d_in[4];   // [32]
    float* out = (float*)d_out;                  // [256,32]

    cudaFuncSetAttribute(esn_main, cudaFuncAttributeMaxDynamicSharedMemorySize, SMEM_TOTAL);

    prep_zero<<<1, 1>>>();
    prep_w<<<(128 * KC2T * 32 + 255) / 256, 256>>>(w_r, w_in);
    prep_x<<<(int)(((size_t)TT * 16 * 8 * 32) / 256), 256>>>(x);
    esn_main<<<NCTA, THREADS, SMEM_TOTAL>>>();
    readout<<<BB, 256>>>(lw, lb, out);
}

// round 3
// speedup vs baseline: 2.4323x; 1.0401x over previous
#include <cuda_runtime.h>
#include <cuda_fp16.h>

// ---------------------------------------------------------------------------
// ESN recurrence, fp16 tensor-core, round 3.
//  - BM=32 x BN=64 tiles, 128 persistent CTAs, 8 warps (2 K-halves x 4 n-pairs).
//  - Each warp: 2 m16 x 2 n8 x 18 kc-pairs -> B smem bytes/mma halved.
//  - h re-read by only 16 CTAs per m-slice (A L2 traffic 8MB/step).
//  - Old h kept in registers (no dependent load in epilogue).
//  - x-part mmas overlapped with barrier wait; all-thread acquire spin.
// ---------------------------------------------------------------------------

#define TT     2048
#define BB     256
#define HH     1024
#define DD     128
#define NCTA   128
#define THREADS 256
#define KC2T   36
#define KEEP0  2028
#define NLAST  20
#define KOUT   (NLAST*HH)

#define SMEM_W_BYTES   (8*KC2T*32*16)    // 147456: [n8 8][kc2 36][lane 32] uint4
#define SMEM_RED_BYTES (8*2*32*16)       // 8192
#define SMEM_TOTAL     (SMEM_W_BYTES + SMEM_RED_BYTES)

// ---- device globals --------------------------------------------------------
__device__ __align__(16) uint4 g_X[(size_t)TT*16*8*32];   // x frags fp16
__device__ __align__(16) uint4 g_W[128*KC2T*32];          // W frags fp16 (kc-pair packed)
__device__ __align__(16) uint4 g_H[2][16][64][32];        // h frags [buf][m16][kc][lane]
__device__ float    g_hist[(size_t)NLAST*BB*HH];
__device__ unsigned g_count;

// ---- helpers ---------------------------------------------------------------
__device__ __forceinline__ unsigned pkh(float a, float b) {
    __half2 t = __floats2half2_rn(a, b);
    return reinterpret_cast<unsigned&>(t);
}
__device__ __forceinline__ void mma16816(float* c, const uint4 a, const uint2 b) {
    asm volatile(
        "mma.sync.aligned.m16n8k16.row.col.f32.f16.f16.f32 "
        "{%0,%1,%2,%3}, {%4,%5,%6,%7}, {%8,%9}, {%0,%1,%2,%3};\n"
        : "+f"(c[0]), "+f"(c[1]), "+f"(c[2]), "+f"(c[3])
        : "r"(a.x), "r"(a.y), "r"(a.z), "r"(a.w), "r"(b.x), "r"(b.y));
}

// 2-m16 span over CNT kc-pairs. A0/A1: frag streams (stride 32 uint4 per kc).
// c layout: [m 2][n 2][4].
template<int CNT>
__device__ __forceinline__ void mma_span2(float* c,
        const uint4* __restrict__ A0, const uint4* __restrict__ A1,
        const uint4* __restrict__ sW4, int n8a, int n8b, int kc2base, int lane) {
    uint4 ra[4][4];
#pragma unroll
    for (int i = 0; i < 4 && i < CNT; i++) {
        ra[i][0] = __ldcg(A0 + (size_t)(2*i)   * 32);
        ra[i][1] = __ldcg(A0 + (size_t)(2*i+1) * 32);
        ra[i][2] = __ldcg(A1 + (size_t)(2*i)   * 32);
        ra[i][3] = __ldcg(A1 + (size_t)(2*i+1) * 32);
    }
#pragma unroll
    for (int j = 0; j < CNT; j++) {
        uint4 b0 = sW4[(size_t)(n8a*KC2T + kc2base + j)*32 + lane];
        uint4 b1 = sW4[(size_t)(n8b*KC2T + kc2base + j)*32 + lane];
        uint4 a00 = ra[j&3][0], a01 = ra[j&3][1];
        uint4 a10 = ra[j&3][2], a11 = ra[j&3][3];
        if (j + 4 < CNT) {
            ra[j&3][0] = __ldcg(A0 + (size_t)(2*(j+4))   * 32);
            ra[j&3][1] = __ldcg(A0 + (size_t)(2*(j+4)+1) * 32);
            ra[j&3][2] = __ldcg(A1 + (size_t)(2*(j+4))   * 32);
            ra[j&3][3] = __ldcg(A1 + (size_t)(2*(j+4)+1) * 32);
        }
        mma16816(c + 0,  a00, make_uint2(b0.x, b0.y));
        mma16816(c + 0,  a01, make_uint2(b0.z, b0.w));
        mma16816(c + 4,  a00, make_uint2(b1.x, b1.y));
        mma16816(c + 4,  a01, make_uint2(b1.z, b1.w));
        mma16816(c + 8,  a10, make_uint2(b0.x, b0.y));
        mma16816(c + 8,  a11, make_uint2(b0.z, b0.w));
        mma16816(c + 12, a10, make_uint2(b1.x, b1.y));
        mma16816(c + 12, a11, make_uint2(b1.z, b1.w));
    }
}

// ---- prep kernels ----------------------------------------------------------
__global__ void prep_zero() { g_count = 0u; }

__global__ void prep_w(const float* __restrict__ w_r, const float* __restrict__ w_in) {
    int i = blockIdx.x * blockDim.x + threadIdx.x;
    if (i >= 128 * KC2T * 32) return;
    int lane = i & 31;
    int kc2  = (i >> 5) % KC2T;
    int n8   = i / (KC2T * 32);
    int n    = n8 * 8 + (lane >> 2);
    unsigned u[4];
#pragma unroll
    for (int s = 0; s < 2; s++) {
        int kc = 2 * kc2 + s;
        int k0 = kc * 16 + (lane & 3) * 2;
        float v[4];
#pragma unroll
        for (int r = 0; r < 4; r++) {
            int k = k0 + ((r >> 1) * 8) + (r & 1);
            v[r] = (k < HH) ? w_r[(size_t)k * HH + n] : w_in[(size_t)(k - HH) * HH + n];
        }
        u[2*s + 0] = pkh(v[0], v[1]);
        u[2*s + 1] = pkh(v[2], v[3]);
    }
    g_W[i] = make_uint4(u[0], u[1], u[2], u[3]);
}

__global__ void prep_x(const float* __restrict__ x) {
    size_t i = (size_t)blockIdx.x * blockDim.x + threadIdx.x;
    if (i >= (size_t)TT * 16 * 8 * 32) return;
    int lane = (int)(i & 31);
    int kcx  = (int)((i >> 5) & 7);
    int m16  = (int)((i >> 8) & 15);
    int t    = (int)(i >> 12);
    int b = m16 * 16 + (lane >> 2);
    int d = kcx * 16 + (lane & 3) * 2;
    const float* p0 = x + ((size_t)b * TT + t) * DD + d;
    const float* p1 = p0 + (size_t)8 * TT * DD;
    float2 a0 = *(const float2*)(p0);
    float2 a1 = *(const float2*)(p1);
    float2 a2 = *(const float2*)(p0 + 8);
    float2 a3 = *(const float2*)(p1 + 8);
    g_X[i] = make_uint4(pkh(a0.x, a0.y), pkh(a1.x, a1.y),
                        pkh(a2.x, a2.y), pkh(a3.x, a3.y));
}

// ---- main persistent kernel ------------------------------------------------
__global__ void __launch_bounds__(THREADS, 1) esn_main() {
    extern __shared__ __align__(16) unsigned char smem[];
    uint4*  sW4  = reinterpret_cast<uint4*>(smem);
    float4* sred = reinterpret_cast<float4*>(smem + SMEM_W_BYTES);

    const int tid   = threadIdx.x;
    const int lane  = tid & 31;
    const int warp  = tid >> 5;
    const int wn    = warp & 3;          // n-pair: n8 local {2wn, 2wn+1}
    const int wk    = warp >> 2;         // K-half
    const int cta_n = blockIdx.x & 15;   // 16 N-tiles (BN=64)
    const int cta_m = blockIdx.x >> 4;   // 8 M-tiles (BM=32)
    const int m16g0 = 2 * cta_m;
    const int m16g1 = m16g0 + 1;
    const int n8a   = 2 * wn;
    const int n8b   = 2 * wn + 1;
    const int kcw   = 4 * cta_n + wn;    // owned h column-chunk
    const int m16o  = m16g0 + wk;        // owned h m16

    // Load W column tile (8 n8 blocks) into smem; resident for all steps.
    {
        const uint4* src = g_W + (size_t)(8 * cta_n) * KC2T * 32;
        for (int i = tid; i < 8 * KC2T * 32; i += THREADS) sW4[i] = src[i];
    }
    __syncthreads();

    float hprev[8];
    unsigned* const cp = &g_count;

    for (int t = 0; t < TT; t++) {
        float c[16];
#pragma unroll
        for (int i = 0; i < 16; i++) c[i] = 0.f;

        // x part first (independent of h) — overlaps with barrier wait below.
        {
            const uint4* X0 = &g_X[(((size_t)t * 16 + m16g0) * 8 + wk * 4) * 32 + lane];
            const uint4* X1 = &g_X[(((size_t)t * 16 + m16g1) * 8 + wk * 4) * 32 + lane];
            mma_span2<2>(c, X0, X1, sW4, n8a, n8b, 32 + wk * 2, lane);
        }

        if (t > 0) {
            // wait: all threads acquire-spin until every CTA stored h_t
            unsigned want = (unsigned)t * NCTA;
            unsigned v;
            do {
                asm volatile("ld.acquire.gpu.global.u32 %0, [%1];"
                             : "=r"(v) : "l"(cp) : "memory");
            } while (v < want);

            const int rb = t & 1;
            const uint4* A0 = &g_H[rb][m16g0][wk * 32][lane];
            const uint4* A1 = &g_H[rb][m16g1][wk * 32][lane];
            mma_span2<16>(c, A0, A1, sW4, n8a, n8b, wk * 16, lane);
        }

        // K-half reduction through smem: ownership split along m.
        {
            int s = wn * 2 + (1 - wk);
            const float* cp8 = c + (1 - wk) * 8;
            sred[(size_t)(s * 2 + 0) * 32 + lane] = make_float4(cp8[0], cp8[1], cp8[2], cp8[3]);
            sred[(size_t)(s * 2 + 1) * 32 + lane] = make_float4(cp8[4], cp8[5], cp8[6], cp8[7]);
        }
        __syncthreads();
        float fin[8];
        {
            int s = wn * 2 + wk;
            float4 r0 = sred[(size_t)(s * 2 + 0) * 32 + lane];
            float4 r1 = sred[(size_t)(s * 2 + 1) * 32 + lane];
            const float* cm = c + wk * 8;
            fin[0] = cm[0] + r0.x; fin[1] = cm[1] + r0.y;
            fin[2] = cm[2] + r0.z; fin[3] = cm[3] + r0.w;
            fin[4] = cm[4] + r1.x; fin[5] = cm[5] + r1.y;
            fin[6] = cm[6] + r1.z; fin[7] = cm[7] + r1.w;
        }

        // blend (old h carried in registers, fp32)
        float hv[8];
        if (t == 0) {
#pragma unroll
            for (int i = 0; i < 8; i++) hv[i] = tanhf(fin[i]);
        } else {
#pragma unroll
            for (int i = 0; i < 8; i++) hv[i] = 0.1f * hprev[i] + 0.9f * tanhf(fin[i]);
        }
#pragma unroll
        for (int i = 0; i < 8; i++) hprev[i] = hv[i];

        uint4 nh = make_uint4(pkh(hv[0], hv[1]), pkh(hv[2], hv[3]),
                              pkh(hv[4], hv[5]), pkh(hv[6], hv[7]));
        __stcg(&g_H[(t + 1) & 1][m16o][kcw][lane], nh);

        // arrive ASAP (hist stores may drift past the barrier)
        if (t < TT - 1) {
            __syncthreads();
            if (tid == 0)
                asm volatile("red.release.gpu.global.add.u32 [%0], %1;"
                             :: "l"(cp), "r"(1u) : "memory");
        }

        if (t >= KEEP0) {
            int r0r = m16o * 16 + (lane >> 2);
            int cb  = kcw * 16 + (lane & 3) * 2;
            size_t base = (size_t)(t - KEEP0) * BB * HH;
            *(float2*)&g_hist[base + (size_t)(r0r)     * HH + cb]     = make_float2(hv[0], hv[1]);
            *(float2*)&g_hist[base + (size_t)(r0r + 8) * HH + cb]     = make_float2(hv[2], hv[3]);
            *(float2*)&g_hist[base + (size_t)(r0r)     * HH + cb + 8] = make_float2(hv[4], hv[5]);
            *(float2*)&g_hist[base + (size_t)(r0r + 8) * HH + cb + 8] = make_float2(hv[6], hv[7]);
        }
    }
}

// ---- readout ---------------------------------------------------------------
__global__ void readout(const float* __restrict__ lw, const float* __restrict__ lb,
                        float* __restrict__ out) {
    int b    = blockIdx.x;
    int warp = threadIdx.x >> 5;
    int lane = threadIdx.x & 31;
    int o0   = warp * 4;
    float a0 = 0.f, a1 = 0.f, a2 = 0.f, a3 = 0.f;
    for (int k = lane; k < KOUT; k += 32) {
        int s = k >> 10, j = k & (HH - 1);
        float hval = g_hist[(size_t)s * BB * HH + (size_t)b * HH + j];
        a0 += hval * __ldg(&lw[(size_t)(o0 + 0) * KOUT + k]);
        a1 += hval * __ldg(&lw[(size_t)(o0 + 1) * KOUT + k]);
        a2 += hval * __ldg(&lw[(size_t)(o0 + 2) * KOUT + k]);
        a3 += hval * __ldg(&lw[(size_t)(o0 + 3) * KOUT + k]);
    }
#pragma unroll
    for (int off = 16; off > 0; off >>= 1) {
        a0 += __shfl_down_sync(0xffffffffu, a0, off);
        a1 += __shfl_down_sync(0xffffffffu, a1, off);
        a2 += __shfl_down_sync(0xffffffffu, a2, off);
        a3 += __shfl_down_sync(0xffffffffu, a3, off);
    }
    if (lane == 0) {
        out[b * 32 + o0 + 0] = a0 + lb[o0 + 0];
        out[b * 32 + o0 + 1] = a1 + lb[o0 + 1];
        out[b * 32 + o0 + 2] = a2 + lb[o0 + 2];
        out[b * 32 + o0 + 3] = a3 + lb[o0 + 3];
    }
}

// ---- launch ----------------------------------------------------------------
extern "C" void kernel_launch(void* const* d_in, const int* in_sizes, int n_in,
                              void* d_out, int out_size) {
    const float* x    = (const float*)d_in[0];   // [256,2048,128]
    const float* w_in = (const float*)d_in[1];   // [128,1024]
    const float* w_r  = (const float*)d_in[2];   // [1024,1024]
    const float* lw   = (const float*)d_in[3];   // [32,20480]
    const float* lb   = (const float*)d_in[4];   // [32]
    float* out = (float*)d_out;                  // [256,32]

    cudaFuncSetAttribute(esn_main, cudaFuncAttributeMaxDynamicSharedMemorySize, SMEM_TOTAL);

    prep_zero<<<1, 1>>>();
    prep_w<<<(128 * KC2T * 32 + 255) / 256, 256>>>(w_r, w_in);
    prep_x<<<(int)(((size_t)TT * 16 * 8 * 32) / 256), 256>>>(x);
    esn_main<<<NCTA, THREADS, SMEM_TOTAL>>>();
    readout<<<BB, 256>>>(lw, lb, out);
}

// round 4
// speedup vs baseline: 2.4908x; 1.0240x over previous
#include <cuda_runtime.h>
#include <cuda_fp16.h>

// ---------------------------------------------------------------------------
// ESN recurrence, fp16 tensor-core, round 4.
//  Key change vs R3: batch rows are independent => 8 independent groups of 16
//  CTAs (group = cta_m). Per-group padded counters, single spinner per CTA,
//  syncthreads wake. No global barrier, no all-thread L2 spin.
// ---------------------------------------------------------------------------

#define TT     2048
#define BB     256
#define HH     1024
#define DD     128
#define NCTA   128
#define THREADS 256
#define KC2T   36
#define KEEP0  2028
#define NLAST  20
#define KOUT   (NLAST*HH)

#define SMEM_W_BYTES   (8*KC2T*32*16)    // 147456
#define SMEM_RED_BYTES (8*2*32*16)       // 8192
#define SMEM_TOTAL     (SMEM_W_BYTES + SMEM_RED_BYTES)

// ---- device globals --------------------------------------------------------
__device__ __align__(16) uint4 g_X[(size_t)TT*16*8*32];
__device__ __align__(16) uint4 g_W[128*KC2T*32];
__device__ __align__(16) uint4 g_H[2][16][64][32];
__device__ float    g_hist[(size_t)NLAST*BB*HH];
__device__ unsigned g_gcount[8*32];      // 8 group counters, 128B apart

// ---- helpers ---------------------------------------------------------------
__device__ __forceinline__ unsigned pkh(float a, float b) {
    __half2 t = __floats2half2_rn(a, b);
    return reinterpret_cast<unsigned&>(t);
}
__device__ __forceinline__ void mma16816(float* c, const uint4 a, const uint2 b) {
    asm volatile(
        "mma.sync.aligned.m16n8k16.row.col.f32.f16.f16.f32 "
        "{%0,%1,%2,%3}, {%4,%5,%6,%7}, {%8,%9}, {%0,%1,%2,%3};\n"
        : "+f"(c[0]), "+f"(c[1]), "+f"(c[2]), "+f"(c[3])
        : "r"(a.x), "r"(a.y), "r"(a.z), "r"(a.w), "r"(b.x), "r"(b.y));
}

template<int CNT>
__device__ __forceinline__ void mma_span2(float* c,
        const uint4* __restrict__ A0, const uint4* __restrict__ A1,
        const uint4* __restrict__ sW4, int n8a, int n8b, int kc2base, int lane) {
    uint4 ra[4][4];
#pragma unroll
    for (int i = 0; i < 4 && i < CNT; i++) {
        ra[i][0] = __ldcg(A0 + (size_t)(2*i)   * 32);
        ra[i][1] = __ldcg(A0 + (size_t)(2*i+1) * 32);
        ra[i][2] = __ldcg(A1 + (size_t)(2*i)   * 32);
        ra[i][3] = __ldcg(A1 + (size_t)(2*i+1) * 32);
    }
#pragma unroll
    for (int j = 0; j < CNT; j++) {
        uint4 b0 = sW4[(size_t)(n8a*KC2T + kc2base + j)*32 + lane];
        uint4 b1 = sW4[(size_t)(n8b*KC2T + kc2base + j)*32 + lane];
        uint4 a00 = ra[j&3][0], a01 = ra[j&3][1];
        uint4 a10 = ra[j&3][2], a11 = ra[j&3][3];
        if (j + 4 < CNT) {
            ra[j&3][0] = __ldcg(A0 + (size_t)(2*(j+4))   * 32);
            ra[j&3][1] = __ldcg(A0 + (size_t)(2*(j+4)+1) * 32);
            ra[j&3][2] = __ldcg(A1 + (size_t)(2*(j+4))   * 32);
            ra[j&3][3] = __ldcg(A1 + (size_t)(2*(j+4)+1) * 32);
        }
        mma16816(c + 0,  a00, make_uint2(b0.x, b0.y));
        mma16816(c + 0,  a01, make_uint2(b0.z, b0.w));
        mma16816(c + 4,  a00, make_uint2(b1.x, b1.y));
        mma16816(c + 4,  a01, make_uint2(b1.z, b1.w));
        mma16816(c + 8,  a10, make_uint2(b0.x, b0.y));
        mma16816(c + 8,  a11, make_uint2(b0.z, b0.w));
        mma16816(c + 12, a10, make_uint2(b1.x, b1.y));
        mma16816(c + 12, a11, make_uint2(b1.z, b1.w));
    }
}

// ---- prep kernels ----------------------------------------------------------
__global__ void prep_zero() {
    int i = threadIdx.x;
    if (i < 8 * 32) g_gcount[i] = 0u;
}

__global__ void prep_w(const float* __restrict__ w_r, const float* __restrict__ w_in) {
    int i = blockIdx.x * blockDim.x + threadIdx.x;
    if (i >= 128 * KC2T * 32) return;
    int lane = i & 31;
    int kc2  = (i >> 5) % KC2T;
    int n8   = i / (KC2T * 32);
    int n    = n8 * 8 + (lane >> 2);
    unsigned u[4];
#pragma unroll
    for (int s = 0; s < 2; s++) {
        int kc = 2 * kc2 + s;
        int k0 = kc * 16 + (lane & 3) * 2;
        float v[4];
#pragma unroll
        for (int r = 0; r < 4; r++) {
            int k = k0 + ((r >> 1) * 8) + (r & 1);
            v[r] = (k < HH) ? w_r[(size_t)k * HH + n] : w_in[(size_t)(k - HH) * HH + n];
        }
        u[2*s + 0] = pkh(v[0], v[1]);
        u[2*s + 1] = pkh(v[2], v[3]);
    }
    g_W[i] = make_uint4(u[0], u[1], u[2], u[3]);
}

__global__ void prep_x(const float* __restrict__ x) {
    size_t i = (size_t)blockIdx.x * blockDim.x + threadIdx.x;
    if (i >= (size_t)TT * 16 * 8 * 32) return;
    int lane = (int)(i & 31);
    int kcx  = (int)((i >> 5) & 7);
    int m16  = (int)((i >> 8) & 15);
    int t    = (int)(i >> 12);
    int b = m16 * 16 + (lane >> 2);
    int d = kcx * 16 + (lane & 3) * 2;
    const float* p0 = x + ((size_t)b * TT + t) * DD + d;
    const float* p1 = p0 + (size_t)8 * TT * DD;
    float2 a0 = *(const float2*)(p0);
    float2 a1 = *(const float2*)(p1);
    float2 a2 = *(const float2*)(p0 + 8);
    float2 a3 = *(const float2*)(p1 + 8);
    g_X[i] = make_uint4(pkh(a0.x, a0.y), pkh(a1.x, a1.y),
                        pkh(a2.x, a2.y), pkh(a3.x, a3.y));
}

// ---- main persistent kernel ------------------------------------------------
__global__ void __launch_bounds__(THREADS, 1) esn_main() {
    extern __shared__ __align__(16) unsigned char smem[];
    uint4*  sW4  = reinterpret_cast<uint4*>(smem);
    float4* sred = reinterpret_cast<float4*>(smem + SMEM_W_BYTES);

    const int tid   = threadIdx.x;
    const int lane  = tid & 31;
    const int warp  = tid >> 5;
    const int wn    = warp & 3;
    const int wk    = warp >> 2;
    const int cta_n = blockIdx.x & 15;   // 16 N-tiles per group
    const int cta_m = blockIdx.x >> 4;   // 8 independent groups
    const int m16g0 = 2 * cta_m;
    const int m16g1 = m16g0 + 1;
    const int n8a   = 2 * wn;
    const int n8b   = 2 * wn + 1;
    const int kcw   = 4 * cta_n + wn;
    const int m16o  = m16g0 + wk;

    {
        const uint4* src = g_W + (size_t)(8 * cta_n) * KC2T * 32;
        for (int i = tid; i < 8 * KC2T * 32; i += THREADS) sW4[i] = src[i];
    }
    __syncthreads();

    float hprev[8];
    unsigned* const cp = &g_gcount[cta_m * 32];   // this group's counter

    for (int t = 0; t < TT; t++) {
        float c[16];
#pragma unroll
        for (int i = 0; i < 16; i++) c[i] = 0.f;

        // x part (independent of h_t) — overlaps group laggards
        {
            const uint4* X0 = &g_X[(((size_t)t * 16 + m16g0) * 8 + wk * 4) * 32 + lane];
            const uint4* X1 = &g_X[(((size_t)t * 16 + m16g1) * 8 + wk * 4) * 32 + lane];
            mma_span2<2>(c, X0, X1, sW4, n8a, n8b, 32 + wk * 2, lane);
        }

        if (t > 0) {
            // single spinner per CTA on the group counter, bar wake
            if (tid == 0) {
                unsigned want = (unsigned)t * 16u;
                unsigned v;
                do {
                    asm volatile("ld.acquire.gpu.global.u32 %0, [%1];"
                                 : "=r"(v) : "l"(cp) : "memory");
                } while (v < want);
            }
            __syncthreads();

            const int rb = t & 1;
            const uint4* A0 = &g_H[rb][m16g0][wk * 32][lane];
            const uint4* A1 = &g_H[rb][m16g1][wk * 32][lane];
            mma_span2<16>(c, A0, A1, sW4, n8a, n8b, wk * 16, lane);
        }

        // K-half reduction through smem
        {
            int s = wn * 2 + (1 - wk);
            const float* cp8 = c + (1 - wk) * 8;
            sred[(size_t)(s * 2 + 0) * 32 + lane] = make_float4(cp8[0], cp8[1], cp8[2], cp8[3]);
            sred[(size_t)(s * 2 + 1) * 32 + lane] = make_float4(cp8[4], cp8[5], cp8[6], cp8[7]);
        }
        __syncthreads();
        float fin[8];
        {
            int s = wn * 2 + wk;
            float4 r0 = sred[(size_t)(s * 2 + 0) * 32 + lane];
            float4 r1 = sred[(size_t)(s * 2 + 1) * 32 + lane];
            const float* cm = c + wk * 8;
            fin[0] = cm[0] + r0.x; fin[1] = cm[1] + r0.y;
            fin[2] = cm[2] + r0.z; fin[3] = cm[3] + r0.w;
            fin[4] = cm[4] + r1.x; fin[5] = cm[5] + r1.y;
            fin[6] = cm[6] + r1.z; fin[7] = cm[7] + r1.w;
        }

        float hv[8];
        if (t == 0) {
#pragma unroll
            for (int i = 0; i < 8; i++) hv[i] = tanhf(fin[i]);
        } else {
#pragma unroll
            for (int i = 0; i < 8; i++) hv[i] = 0.1f * hprev[i] + 0.9f * tanhf(fin[i]);
        }
#pragma unroll
        for (int i = 0; i < 8; i++) hprev[i] = hv[i];

        uint4 nh = make_uint4(pkh(hv[0], hv[1]), pkh(hv[2], hv[3]),
                              pkh(hv[4], hv[5]), pkh(hv[6], hv[7]));
        __stcg(&g_H[(t + 1) & 1][m16o][kcw][lane], nh);

        // arrive on the group counter ASAP
        if (t < TT - 1) {
            __syncthreads();
            if (tid == 0)
                asm volatile("red.release.gpu.global.add.u32 [%0], %1;"
                             :: "l"(cp), "r"(1u) : "memory");
        }

        if (t >= KEEP0) {
            int r0r = m16o * 16 + (lane >> 2);
            int cb  = kcw * 16 + (lane & 3) * 2;
            size_t base = (size_t)(t - KEEP0) * BB * HH;
            *(float2*)&g_hist[base + (size_t)(r0r)     * HH + cb]     = make_float2(hv[0], hv[1]);
            *(float2*)&g_hist[base + (size_t)(r0r + 8) * HH + cb]     = make_float2(hv[2], hv[3]);
            *(float2*)&g_hist[base + (size_t)(r0r)     * HH + cb + 8] = make_float2(hv[4], hv[5]);
            *(float2*)&g_hist[base + (size_t)(r0r + 8) * HH + cb + 8] = make_float2(hv[6], hv[7]);
        }
    }
}

// ---- readout ---------------------------------------------------------------
__global__ void readout(const float* __restrict__ lw, const float* __restrict__ lb,
                        float* __restrict__ out) {
    int b    = blockIdx.x;
    int warp = threadIdx.x >> 5;
    int lane = threadIdx.x & 31;
    int o0   = warp * 4;
    float a0 = 0.f, a1 = 0.f, a2 = 0.f, a3 = 0.f;
    for (int k = lane; k < KOUT; k += 32) {
        int s = k >> 10, j = k & (HH - 1);
        float hval = g_hist[(size_t)s * BB * HH + (size_t)b * HH + j];
        a0 += hval * __ldg(&lw[(size_t)(o0 + 0) * KOUT + k]);
        a1 += hval * __ldg(&lw[(size_t)(o0 + 1) * KOUT + k]);
        a2 += hval * __ldg(&lw[(size_t)(o0 + 2) * KOUT + k]);
        a3 += hval * __ldg(&lw[(size_t)(o0 + 3) * KOUT + k]);
    }
#pragma unroll
    for (int off = 16; off > 0; off >>= 1) {
        a0 += __shfl_down_sync(0xffffffffu, a0, off);
        a1 += __shfl_down_sync(0xffffffffu, a1, off);
        a2 += __shfl_down_sync(0xffffffffu, a2, off);
        a3 += __shfl_down_sync(0xffffffffu, a3, off);
    }
    if (lane == 0) {
        out[b * 32 + o0 + 0] = a0 + lb[o0 + 0];
        out[b * 32 + o0 + 1] = a1 + lb[o0 + 1];
        out[b * 32 + o0 + 2] = a2 + lb[o0 + 2];
        out[b * 32 + o0 + 3] = a3 + lb[o0 + 3];
    }
}

// ---- launch ----------------------------------------------------------------
extern "C" void kernel_launch(void* const* d_in, const int* in_sizes, int n_in,
                              void* d_out, int out_size) {
    const float* x    = (const float*)d_in[0];
    const float* w_in = (const float*)d_in[1];
    const float* w_r  = (const float*)d_in[2];
    const float* lw   = (const float*)d_in[3];
    const float* lb   = (const float*)d_in[4];
    float* out = (float*)d_out;

    cudaFuncSetAttribute(esn_main, cudaFuncAttributeMaxDynamicSharedMemorySize, SMEM_TOTAL);

    prep_zero<<<1, 256>>>();
    prep_w<<<(128 * KC2T * 32 + 255) / 256, 256>>>(w_r, w_in);
    prep_x<<<(int)(((size_t)TT * 16 * 8 * 32) / 256), 256>>>(x);
    esn_main<<<NCTA, THREADS, SMEM_TOTAL>>>();
    readout<<<BB, 256>>>(lw, lb, out);
}

// round 7
// speedup vs baseline: 2.5207x; 1.0120x over previous
#include <cuda_runtime.h>
#include <cuda_fp16.h>

// ---------------------------------------------------------------------------
// ESN recurrence, fp16 tensor-core, round 7 (R5/R6 theory, plain R4 spin).
//  512 threads (16 warps) per CTA, K split 4 ways -> 4 warps/SMSP latency
//  hiding. 4-way K reduction in smem; 8 owner warps do epilogue.
//  8 independent groups of 16 CTAs sync via padded counters.
// ---------------------------------------------------------------------------

#define TT     2048
#define BB     256
#define HH     1024
#define DD     128
#define NCTA   128
#define THREADS 512
#define KC2T   36
#define KEEP0  2028
#define NLAST  20
#define KOUT   (NLAST*HH)

#define SMEM_W_BYTES   (8*KC2T*32*16)    // 147456
#define SMEM_RED_BYTES (8*3*2*32*16)     // 24576
#define SMEM_TOTAL     (SMEM_W_BYTES + SMEM_RED_BYTES)

// ---- device globals --------------------------------------------------------
__device__ __align__(16) uint4 g_X[(size_t)TT*16*8*32];
__device__ __align__(16) uint4 g_W[128*KC2T*32];
__device__ __align__(16) uint4 g_H[2][16][64][32];
__device__ float    g_hist[(size_t)NLAST*BB*HH];
__device__ unsigned g_gcount[8*32];      // 8 group counters, 128B apart

// ---- helpers ---------------------------------------------------------------
__device__ __forceinline__ unsigned pkh(float a, float b) {
    __half2 t = __floats2half2_rn(a, b);
    return reinterpret_cast<unsigned&>(t);
}
__device__ __forceinline__ void mma16816(float* c, const uint4 a, const uint2 b) {
    asm volatile(
        "mma.sync.aligned.m16n8k16.row.col.f32.f16.f16.f32 "
        "{%0,%1,%2,%3}, {%4,%5,%6,%7}, {%8,%9}, {%0,%1,%2,%3};\n"
        : "+f"(c[0]), "+f"(c[1]), "+f"(c[2]), "+f"(c[3])
        : "r"(a.x), "r"(a.y), "r"(a.z), "r"(a.w), "r"(b.x), "r"(b.y));
}

// 2-m16 span over CNT kc-pairs, ring depth 2. c layout: [m 2][n 2][4].
template<int CNT>
__device__ __forceinline__ void mma_span2(float* c,
        const uint4* __restrict__ A0, const uint4* __restrict__ A1,
        const uint4* __restrict__ sW4, int n8a, int n8b, int kc2base, int lane) {
    uint4 ra[2][4];
#pragma unroll
    for (int i = 0; i < 2 && i < CNT; i++) {
        ra[i][0] = __ldcg(A0 + (size_t)(2*i)   * 32);
        ra[i][1] = __ldcg(A0 + (size_t)(2*i+1) * 32);
        ra[i][2] = __ldcg(A1 + (size_t)(2*i)   * 32);
        ra[i][3] = __ldcg(A1 + (size_t)(2*i+1) * 32);
    }
#pragma unroll
    for (int j = 0; j < CNT; j++) {
        uint4 b0 = sW4[(size_t)(n8a*KC2T + kc2base + j)*32 + lane];
        uint4 b1 = sW4[(size_t)(n8b*KC2T + kc2base + j)*32 + lane];
        uint4 a00 = ra[j&1][0], a01 = ra[j&1][1];
        uint4 a10 = ra[j&1][2], a11 = ra[j&1][3];
        if (j + 2 < CNT) {
            ra[j&1][0] = __ldcg(A0 + (size_t)(2*(j+2))   * 32);
            ra[j&1][1] = __ldcg(A0 + (size_t)(2*(j+2)+1) * 32);
            ra[j&1][2] = __ldcg(A1 + (size_t)(2*(j+2))   * 32);
            ra[j&1][3] = __ldcg(A1 + (size_t)(2*(j+2)+1) * 32);
        }
        mma16816(c + 0,  a00, make_uint2(b0.x, b0.y));
        mma16816(c + 0,  a01, make_uint2(b0.z, b0.w));
        mma16816(c + 4,  a00, make_uint2(b1.x, b1.y));
        mma16816(c + 4,  a01, make_uint2(b1.z, b1.w));
        mma16816(c + 8,  a10, make_uint2(b0.x, b0.y));
        mma16816(c + 8,  a11, make_uint2(b0.z, b0.w));
        mma16816(c + 12, a10, make_uint2(b1.x, b1.y));
        mma16816(c + 12, a11, make_uint2(b1.z, b1.w));
    }
}

// ---- prep kernels ----------------------------------------------------------
__global__ void prep_zero() {
    int i = threadIdx.x;
    if (i < 8 * 32) g_gcount[i] = 0u;
}

__global__ void prep_w(const float* __restrict__ w_r, const float* __restrict__ w_in) {
    int i = blockIdx.x * blockDim.x + threadIdx.x;
    if (i >= 128 * KC2T * 32) return;
    int lane = i & 31;
    int kc2  = (i >> 5) % KC2T;
    int n8   = i / (KC2T * 32);
    int n    = n8 * 8 + (lane >> 2);
    unsigned u[4];
#pragma unroll
    for (int s = 0; s < 2; s++) {
        int kc = 2 * kc2 + s;
        int k0 = kc * 16 + (lane & 3) * 2;
        float v[4];
#pragma unroll
        for (int r = 0; r < 4; r++) {
            int k = k0 + ((r >> 1) * 8) + (r & 1);
            v[r] = (k < HH) ? w_r[(size_t)k * HH + n] : w_in[(size_t)(k - HH) * HH + n];
        }
        u[2*s + 0] = pkh(v[0], v[1]);
        u[2*s + 1] = pkh(v[2], v[3]);
    }
    g_W[i] = make_uint4(u[0], u[1], u[2], u[3]);
}

__global__ void prep_x(const float* __restrict__ x) {
    size_t i = (size_t)blockIdx.x * blockDim.x + threadIdx.x;
    if (i >= (size_t)TT * 16 * 8 * 32) return;
    int lane = (int)(i & 31);
    int kcx  = (int)((i >> 5) & 7);
    int m16  = (int)((i >> 8) & 15);
    int t    = (int)(i >> 12);
    int b = m16 * 16 + (lane >> 2);
    int d = kcx * 16 + (lane & 3) * 2;
    const float* p0 = x + ((size_t)b * TT + t) * DD + d;
    const float* p1 = p0 + (size_t)8 * TT * DD;
    float2 a0 = *(const float2*)(p0);
    float2 a1 = *(const float2*)(p1);
    float2 a2 = *(const float2*)(p0 + 8);
    float2 a3 = *(const float2*)(p1 + 8);
    g_X[i] = make_uint4(pkh(a0.x, a0.y), pkh(a1.x, a1.y),
                        pkh(a2.x, a2.y), pkh(a3.x, a3.y));
}

// ---- main persistent kernel ------------------------------------------------
__global__ void __launch_bounds__(THREADS, 1) esn_main() {
    extern __shared__ __align__(16) unsigned char smem[];
    uint4*  sW4  = reinterpret_cast<uint4*>(smem);
    float4* sred = reinterpret_cast<float4*>(smem + SMEM_W_BYTES);

    const int tid   = threadIdx.x;
    const int lane  = tid & 31;
    const int warp  = tid >> 5;
    const int wn    = warp & 3;          // n-pair
    const int wq    = warp >> 2;         // K-quarter 0..3
    const int cta_n = blockIdx.x & 15;   // 16 N-tiles per group
    const int cta_m = blockIdx.x >> 4;   // 8 independent groups
    const int m16g0 = 2 * cta_m;
    const int m16g1 = m16g0 + 1;
    const int n8a   = 2 * wn;
    const int n8b   = 2 * wn + 1;
    const bool owner = (wq < 2);         // owns fragment (m16g0+wq, wn)
    const int m16o  = m16g0 + wq;        // valid when owner
    const int kcw   = 4 * cta_n + wn;

    {
        const uint4* src = g_W + (size_t)(8 * cta_n) * KC2T * 32;
        for (int i = tid; i < 8 * KC2T * 32; i += THREADS) sW4[i] = src[i];
    }
    __syncthreads();

    float hprev[8];
    unsigned* const cp = &g_gcount[cta_m * 32];

    for (int t = 0; t < TT; t++) {
        float c[16];
#pragma unroll
        for (int i = 0; i < 16; i++) c[i] = 0.f;

        // pre-barrier: this quarter's x kc-pair (kcx 2*wq, 2*wq+1)
        {
            const uint4* X0 = &g_X[(((size_t)t * 16 + m16g0) * 8 + 2 * wq) * 32 + lane];
            const uint4* X1 = &g_X[(((size_t)t * 16 + m16g1) * 8 + 2 * wq) * 32 + lane];
            mma_span2<1>(c, X0, X1, sW4, n8a, n8b, 32 + wq, lane);
        }

        if (t > 0) {
            if (tid == 0) {
                unsigned want = (unsigned)t * 16u;
                unsigned v;
                do {
                    asm volatile("ld.acquire.gpu.global.u32 %0, [%1];"
                                 : "=r"(v) : "l"(cp) : "memory");
                } while (v < want);
            }
            __syncthreads();

            const int rb = t & 1;
            const uint4* A0 = &g_H[rb][m16g0][16 * wq][lane];
            const uint4* A1 = &g_H[rb][m16g1][16 * wq][lane];
            mma_span2<8>(c, A0, A1, sW4, n8a, n8b, 8 * wq, lane);
        }

        // 4-way K reduction through smem.
#pragma unroll
        for (int mi = 0; mi < 2; mi++) {
            if (wq != mi) {
                int src = wq - (wq > mi ? 1 : 0);
                int base = (((mi * 4 + wn) * 3 + src) * 2) * 32 + lane;
                const float* p = c + mi * 8;
                sred[base]      = make_float4(p[0], p[1], p[2], p[3]);
                sred[base + 32] = make_float4(p[4], p[5], p[6], p[7]);
            }
        }
        __syncthreads();

        float hv[8];
        if (owner) {
            float fin[8];
            const float* cm = c + wq * 8;
#pragma unroll
            for (int i = 0; i < 8; i++) fin[i] = cm[i];
#pragma unroll
            for (int src = 0; src < 3; src++) {
                int base = (((wq * 4 + wn) * 3 + src) * 2) * 32 + lane;
                float4 r0 = sred[base];
                float4 r1 = sred[base + 32];
                fin[0] += r0.x; fin[1] += r0.y; fin[2] += r0.z; fin[3] += r0.w;
                fin[4] += r1.x; fin[5] += r1.y; fin[6] += r1.z; fin[7] += r1.w;
            }

            if (t == 0) {
#pragma unroll
                for (int i = 0; i < 8; i++) hv[i] = tanhf(fin[i]);
            } else {
#pragma unroll
                for (int i = 0; i < 8; i++) hv[i] = 0.1f * hprev[i] + 0.9f * tanhf(fin[i]);
            }
#pragma unroll
            for (int i = 0; i < 8; i++) hprev[i] = hv[i];

            uint4 nh = make_uint4(pkh(hv[0], hv[1]), pkh(hv[2], hv[3]),
                                  pkh(hv[4], hv[5]), pkh(hv[6], hv[7]));
            __stcg(&g_H[(t + 1) & 1][m16o][kcw][lane], nh);
        }

        // arrive on the group counter ASAP; hist writes after (off critical path)
        if (t < TT - 1) {
            __syncthreads();
            if (tid == 0)
                asm volatile("red.release.gpu.global.add.u32 [%0], %1;"
                             :: "l"(cp), "r"(1u) : "memory");
        }

        if (owner && t >= KEEP0) {
            int r0r = m16o * 16 + (lane >> 2);
            int cb  = kcw * 16 + (lane & 3) * 2;
            size_t base = (size_t)(t - KEEP0) * BB * HH;
            *(float2*)&g_hist[base + (size_t)(r0r)     * HH + cb]     = make_float2(hv[0], hv[1]);
            *(float2*)&g_hist[base + (size_t)(r0r + 8) * HH + cb]     = make_float2(hv[2], hv[3]);
            *(float2*)&g_hist[base + (size_t)(r0r)     * HH + cb + 8] = make_float2(hv[4], hv[5]);
            *(float2*)&g_hist[base + (size_t)(r0r + 8) * HH + cb + 8] = make_float2(hv[6], hv[7]);
        }
    }
}

// ---- readout ---------------------------------------------------------------
__global__ void readout(const float* __restrict__ lw, const float* __restrict__ lb,
                        float* __restrict__ out) {
    int b    = blockIdx.x;
    int warp = threadIdx.x >> 5;
    int lane = threadIdx.x & 31;
    int o0   = warp * 4;
    float a0 = 0.f, a1 = 0.f, a2 = 0.f, a3 = 0.f;
    for (int k = lane; k < KOUT; k += 32) {
        int s = k >> 10, j = k & (HH - 1);
        float hval = g_hist[(size_t)s * BB * HH + (size_t)b * HH + j];
        a0 += hval * __ldg(&lw[(size_t)(o0 + 0) * KOUT + k]);
        a1 += hval * __ldg(&lw[(size_t)(o0 + 1) * KOUT + k]);
        a2 += hval * __ldg(&lw[(size_t)(o0 + 2) * KOUT + k]);
        a3 += hval * __ldg(&lw[(size_t)(o0 + 3) * KOUT + k]);
    }
#pragma unroll
    for (int off = 16; off > 0; off >>= 1) {
        a0 += __shfl_down_sync(0xffffffffu, a0, off);
        a1 += __shfl_down_sync(0xffffffffu, a1, off);
        a2 += __shfl_down_sync(0xffffffffu, a2, off);
        a3 += __shfl_down_sync(0xffffffffu, a3, off);
    }
    if (lane == 0) {
        out[b * 32 + o0 + 0] = a0 + lb[o0 + 0];
        out[b * 32 + o0 + 1] = a1 + lb[o0 + 1];
        out[b * 32 + o0 + 2] = a2 + lb[o0 + 2];
        out[b * 32 + o0 + 3] = a3 + lb[o0 + 3];
    }
}

// ---- launch ----------------------------------------------------------------
extern "C" void kernel_launch(void* const* d_in, const int* in_sizes, int n_in,
                              void* d_out, int out_size) {
    const float* x    = (const float*)d_in[0];
    const float* w_in = (const float*)d_in[1];
    const float* w_r  = (const float*)d_in[2];
    const float* lw   = (const float*)d_in[3];
    const float* lb   = (const float*)d_in[4];
    float* out = (float*)d_out;

    cudaFuncSetAttribute(esn_main, cudaFuncAttributeMaxDynamicSharedMemorySize, SMEM_TOTAL);

    prep_zero<<<1, 256>>>();
    prep_w<<<(128 * KC2T * 32 + 255) / 256, 256>>>(w_r, w_in);
    prep_x<<<(int)(((size_t)TT * 16 * 8 * 32) / 256), 256>>>(x);
    esn_main<<<NCTA, THREADS, SMEM_TOTAL>>>();
    readout<<<BB, 256>>>(lw, lb, out);
}